// round 2
// baseline (speedup 1.0000x reference)
#include <cuda_runtime.h>
#include <math.h>

#define TT 2048
#define DD 256
#define NH 16      // B*CELLS heads
#define NB 2
#define NC 8

// Scratch (static device allocation — allowed)
__device__ float g_nx[(size_t)NH * TT * DD];
__device__ float g_qkv[(size_t)NH * TT * DD];

// ---------------------------------------------------------------------------
// Kernel 1: LayerNorm  x -> g_nx     (one block per row of 256)
// ---------------------------------------------------------------------------
__global__ __launch_bounds__(256) void ln_kernel(const float* __restrict__ x) {
    int row = blockIdx.x;
    int tid = threadIdx.x;
    float v = x[(size_t)row * DD + tid];
    float s1 = v, s2 = v * v;
#pragma unroll
    for (int off = 16; off; off >>= 1) {
        s1 += __shfl_xor_sync(0xffffffffu, s1, off);
        s2 += __shfl_xor_sync(0xffffffffu, s2, off);
    }
    __shared__ float r1[8], r2[8];
    int w = tid >> 5, l = tid & 31;
    if (l == 0) { r1[w] = s1; r2[w] = s2; }
    __syncthreads();
    float S1 = 0.f, S2 = 0.f;
#pragma unroll
    for (int i = 0; i < 8; i++) { S1 += r1[i]; S2 += r2[i]; }
    float mu  = S1 * (1.0f / DD);
    float var = S2 * (1.0f / DD) - mu * mu;
    float rs  = rsqrtf(var + 1e-5f);
    g_nx[(size_t)row * DD + tid] = (v - mu) * rs;
}

// ---------------------------------------------------------------------------
// Kernel 2: GEMM  g_qkv = g_nx @ gate   (M=32768, N=256, K=256)
// BM=128, BN=128, BK=16, 256 threads, 8x8 microtile
// ---------------------------------------------------------------------------
__global__ __launch_bounds__(256) void gemm_qkv_kernel(const float* __restrict__ G) {
    __shared__ float As[16][128];
    __shared__ float Bs[16][128];
    int tid = threadIdx.x;
    int bm = blockIdx.x * 128;
    int bn = blockIdx.y * 128;
    int tm = (tid >> 4) * 8, tn = (tid & 15) * 8;
    float acc[8][8];
#pragma unroll
    for (int i = 0; i < 8; i++)
#pragma unroll
        for (int j = 0; j < 8; j++) acc[i][j] = 0.f;

    for (int k0 = 0; k0 < 256; k0 += 16) {
#pragma unroll
        for (int u = 0; u < 2; u++) {
            int i4 = tid * 2 + u;              // 0..511
            int m  = i4 >> 2;                  // 0..127
            int kc = (i4 & 3) << 2;            // 0,4,8,12
            float4 a = *(const float4*)(g_nx + (size_t)(bm + m) * 256 + k0 + kc);
            As[kc + 0][m] = a.x; As[kc + 1][m] = a.y;
            As[kc + 2][m] = a.z; As[kc + 3][m] = a.w;
            int kr = i4 >> 5;                  // 0..15
            int nc = (i4 & 31) << 2;           // 0..124
            *(float4*)&Bs[kr][nc] = *(const float4*)(G + (size_t)(k0 + kr) * 256 + bn + nc);
        }
        __syncthreads();
#pragma unroll
        for (int k = 0; k < 16; k++) {
            float4 a0 = *(const float4*)&As[k][tm];
            float4 a1 = *(const float4*)&As[k][tm + 4];
            float4 b0 = *(const float4*)&Bs[k][tn];
            float4 b1 = *(const float4*)&Bs[k][tn + 4];
            float av[8] = {a0.x, a0.y, a0.z, a0.w, a1.x, a1.y, a1.z, a1.w};
            float bv[8] = {b0.x, b0.y, b0.z, b0.w, b1.x, b1.y, b1.z, b1.w};
#pragma unroll
            for (int i = 0; i < 8; i++)
#pragma unroll
                for (int j = 0; j < 8; j++)
                    acc[i][j] = fmaf(av[i], bv[j], acc[i][j]);
        }
        __syncthreads();
    }
#pragma unroll
    for (int i = 0; i < 8; i++) {
        size_t off = (size_t)(bm + tm + i) * 256 + bn + tn;
        float4 o0 = {acc[i][0], acc[i][1], acc[i][2], acc[i][3]};
        float4 o1 = {acc[i][4], acc[i][5], acc[i][6], acc[i][7]};
        *(float4*)(g_qkv + off)     = o0;
        *(float4*)(g_qkv + off + 4) = o1;
    }
}

// ---------------------------------------------------------------------------
// Kernel 3: flash attention (causal), Q=K=V=g_qkv per head.
// out = x + softmax(QK^T/16) @ V.   BM=BN=64, 256 threads.
// smem: sQ[64][256] + sKV[64][256] (row-major, for P@V)
//       + sKVt[256][68] (d-major, padded, for QK^T) + sS[64][64] + stats
// ---------------------------------------------------------------------------
#define ATT_SMEM_FLOATS (64*256 + 64*256 + 256*68 + 64*64 + 192)

__global__ __launch_bounds__(256, 1) void attn_kernel(const float* __restrict__ x,
                                                      float* __restrict__ out) {
    extern __shared__ float sm[];
    float* sQ   = sm;                       // 16384
    float* sKV  = sQ + 64 * 256;            // 16384
    float* sKVt = sKV + 64 * 256;           // 17408 (stride 68)
    float* sS   = sKVt + 256 * 68;          // 4096
    float* sM   = sS + 64 * 64;
    float* sL   = sM + 64;
    float* sAl  = sL + 64;

    int tid  = threadIdx.x;
    int head = blockIdx.y;
    int qt   = (int)gridDim.x - 1 - (int)blockIdx.x;   // big blocks first
    int q0   = qt * 64;
    const float* qkv = g_qkv + (size_t)head * TT * DD;

    // load Q tile
    for (int idx = tid; idx < 64 * 64; idx += 256) {
        int row = idx >> 6, d4 = idx & 63;
        ((float4*)sQ)[row * 64 + d4] =
            ((const float4*)(qkv + (size_t)(q0 + row) * DD))[d4];
    }
    if (tid < 64) { sM[tid] = -1e30f; sL[tid] = 0.f; }

    int ty = tid >> 4, tx = tid & 15;   // S stage: rows ty*4.., cols tx*4..
    int rg = tid >> 5, cg = tid & 31;   // O stage: rows rg*8.., cols cg*8..

    float accO[8][8];
#pragma unroll
    for (int i = 0; i < 8; i++)
#pragma unroll
        for (int j = 0; j < 8; j++) accO[i][j] = 0.f;

    for (int jt = 0; jt <= qt; jt++) {
        __syncthreads();   // protect sKV/sS/sAl from previous iteration readers
        int j0 = jt * 64;
        // load KV tile: row-major + d-major transposed
        for (int idx = tid; idx < 64 * 64; idx += 256) {
            int row = idx >> 6, d4 = idx & 63;
            float4 v = ((const float4*)(qkv + (size_t)(j0 + row) * DD))[d4];
            ((float4*)sKV)[row * 64 + d4] = v;
            int db = d4 << 2;
            sKVt[(db + 0) * 68 + row] = v.x;
            sKVt[(db + 1) * 68 + row] = v.y;
            sKVt[(db + 2) * 68 + row] = v.z;
            sKVt[(db + 3) * 68 + row] = v.w;
        }
        __syncthreads();

        // ---- S = Q K^T  (4x4 microtile per thread) ----
        float accS[4][4];
#pragma unroll
        for (int i = 0; i < 4; i++)
#pragma unroll
            for (int j = 0; j < 4; j++) accS[i][j] = 0.f;

#pragma unroll 4
        for (int d4 = 0; d4 < 64; d4++) {
            float4 q[4];
#pragma unroll
            for (int i = 0; i < 4; i++)
                q[i] = ((const float4*)(sQ + (ty * 4 + i) * 256))[d4];
            const float* ktb = sKVt + (size_t)(d4 << 2) * 68;
            float4 k0 = ((const float4*)(ktb      ))[tx];
            float4 k1 = ((const float4*)(ktb +  68))[tx];
            float4 k2 = ((const float4*)(ktb + 136))[tx];
            float4 k3 = ((const float4*)(ktb + 204))[tx];
#pragma unroll
            for (int i = 0; i < 4; i++) {
                accS[i][0] += q[i].x * k0.x + q[i].y * k1.x + q[i].z * k2.x + q[i].w * k3.x;
                accS[i][1] += q[i].x * k0.y + q[i].y * k1.y + q[i].z * k2.y + q[i].w * k3.y;
                accS[i][2] += q[i].x * k0.z + q[i].y * k1.z + q[i].z * k2.z + q[i].w * k3.z;
                accS[i][3] += q[i].x * k0.w + q[i].y * k1.w + q[i].z * k2.w + q[i].w * k3.w;
            }
        }

        // ---- online softmax over this tile's 64 cols ----
        bool diag = (jt == qt);
#pragma unroll
        for (int i = 0; i < 4; i++) {
            int r = ty * 4 + i;
            float sx = accS[i][0] * 0.0625f;
            float sy = accS[i][1] * 0.0625f;
            float sz = accS[i][2] * 0.0625f;
            float sw = accS[i][3] * 0.0625f;
            if (diag) {   // j0 == q0: mask col > row (relative)
                int c = tx * 4;
                if (c + 0 > r) sx = -1e30f;
                if (c + 1 > r) sy = -1e30f;
                if (c + 2 > r) sz = -1e30f;
                if (c + 3 > r) sw = -1e30f;
            }
            float rmax = fmaxf(fmaxf(sx, sy), fmaxf(sz, sw));
#pragma unroll
            for (int off = 8; off; off >>= 1)
                rmax = fmaxf(rmax, __shfl_xor_sync(0xffffffffu, rmax, off));
            float mold = sM[r];
            float mnew = fmaxf(mold, rmax);
            float al   = __expf(mold - mnew);
            float px = __expf(sx - mnew);
            float py = __expf(sy - mnew);
            float pz = __expf(sz - mnew);
            float pw = __expf(sw - mnew);
            float rsum = (px + py) + (pz + pw);
#pragma unroll
            for (int off = 8; off; off >>= 1)
                rsum += __shfl_xor_sync(0xffffffffu, rsum, off);
            float4 pv = {px, py, pz, pw};
            ((float4*)(sS + r * 64))[tx] = pv;
            __syncwarp();
            if (tx == 0) { sM[r] = mnew; sL[r] = sL[r] * al + rsum; sAl[r] = al; }
        }
        __syncthreads();

        // ---- O = O*alpha + P @ V  (V == KV tile, row-major) ----
#pragma unroll
        for (int i = 0; i < 8; i++) {
            float al = sAl[rg * 8 + i];
#pragma unroll
            for (int j = 0; j < 8; j++) accO[i][j] *= al;
        }
#pragma unroll 2
        for (int kk = 0; kk < 64; kk++) {
            const float* vrow = sKV + kk * 256;
            float4 v0 = ((const float4*)vrow)[cg * 2];
            float4 v1 = ((const float4*)vrow)[cg * 2 + 1];
#pragma unroll
            for (int i = 0; i < 8; i++) {
                float p = sS[(rg * 8 + i) * 64 + kk];
                accO[i][0] = fmaf(p, v0.x, accO[i][0]);
                accO[i][1] = fmaf(p, v0.y, accO[i][1]);
                accO[i][2] = fmaf(p, v0.z, accO[i][2]);
                accO[i][3] = fmaf(p, v0.w, accO[i][3]);
                accO[i][4] = fmaf(p, v1.x, accO[i][4]);
                accO[i][5] = fmaf(p, v1.y, accO[i][5]);
                accO[i][6] = fmaf(p, v1.z, accO[i][6]);
                accO[i][7] = fmaf(p, v1.w, accO[i][7]);
            }
        }
    }
    __syncthreads();

    // final: out = x + O / l
    size_t base = (size_t)head * TT * DD;
#pragma unroll
    for (int i = 0; i < 8; i++) {
        int r = rg * 8 + i;
        float inv = 1.0f / sL[r];
        size_t off = base + (size_t)(q0 + r) * DD + cg * 8;
        float4 x0 = *(const float4*)(x + off);
        float4 x1 = *(const float4*)(x + off + 4);
        float4 o0 = {x0.x + accO[i][0] * inv, x0.y + accO[i][1] * inv,
                     x0.z + accO[i][2] * inv, x0.w + accO[i][3] * inv};
        float4 o1 = {x1.x + accO[i][4] * inv, x1.y + accO[i][5] * inv,
                     x1.z + accO[i][6] * inv, x1.w + accO[i][7] * inv};
        *(float4*)(out + off)     = o0;
        *(float4*)(out + off + 4) = o1;
    }
}

// ---------------------------------------------------------------------------
// Kernel 4: cell mixing + tanh residual + pulse.  In-place on out.
// Each thread owns one (b,t,d) fiber across all 8 cells -> no races.
// ---------------------------------------------------------------------------
__global__ __launch_bounds__(256) void epi_kernel(float* __restrict__ out,
                                                  const float* __restrict__ inh,
                                                  const float* __restrict__ ph,
                                                  const float* __restrict__ amb) {
    __shared__ float sI[64], sP[8], sA[8];
    int tid = threadIdx.x;
    if (tid < 64) sI[tid] = inh[tid];
    if (tid < 8) { sP[tid] = ph[tid]; sA[tid] = amb[tid]; }
    __syncthreads();
    size_t idx = (size_t)blockIdx.x * 256 + tid;   // 0 .. B*T*D-1
    int d = (int)(idx & 255);
    int t = (int)((idx >> 8) & 2047);
    int b = (int)(idx >> 19);
    size_t base = (size_t)b * ((size_t)NC * TT * DD) + (size_t)t * DD + d;
    float xv[8];
#pragma unroll
    for (int c = 0; c < 8; c++) xv[c] = out[base + (size_t)c * TT * DD];
#pragma unroll
    for (int k = 0; k < 8; k++) {
        float comp = 0.f;
#pragma unroll
        for (int c = 0; c < 8; c++) comp = fmaf(xv[c], sI[c * 8 + k], comp);
        float x2 = xv[k] + tanhf(comp);
        float r  = x2 + 0.02f * sinf(fmaf(x2, sA[k], sP[k]));
        out[base + (size_t)k * TT * DD] = r;
    }
}

// ---------------------------------------------------------------------------
extern "C" void kernel_launch(void* const* d_in, const int* in_sizes, int n_in,
                              void* d_out, int out_size) {
    const float* x    = (const float*)d_in[0];
    // d_in[1] = mask (causal by construction; handled analytically)
    const float* gate = (const float*)d_in[2];
    const float* inh  = (const float*)d_in[3];
    const float* ph   = (const float*)d_in[4];
    const float* amb  = (const float*)d_in[5];
    float* out = (float*)d_out;

    ln_kernel<<<NH * TT, 256>>>(x);
    gemm_qkv_kernel<<<dim3(256, 2), 256>>>(gate);

    static const int smem_bytes = ATT_SMEM_FLOATS * 4;
    cudaFuncSetAttribute(attn_kernel, cudaFuncAttributeMaxDynamicSharedMemorySize,
                         smem_bytes);
    attn_kernel<<<dim3(32, NH), 256, smem_bytes>>>(x, out);

    epi_kernel<<<(NB * TT * DD) / 256, 256>>>(out, inh, ph, amb);
}